// round 17
// baseline (speedup 1.0000x reference)
#include <cuda_runtime.h>
#include <cuda_bf16.h>

#define BSEQ 512
#define LSEQ 512
#define AA   20
#define CCH  8
#define NREST 8
#define NPRE 9
#define GRID (NPRE + BSEQ * 2)

#define MMA_BF16(C, A, B) \
    asm volatile("mma.sync.aligned.m16n8k16.row.col.f32.bf16.bf16.f32 " \
                 "{%0,%1,%2,%3}, {%4,%5,%6,%7}, {%8,%9}, {%0,%1,%2,%3};" \
                 : "+f"((C)[0]), "+f"((C)[1]), "+f"((C)[2]), "+f"((C)[3]) \
                 : "r"((A)[0]), "r"((A)[1]), "r"((A)[2]), "r"((A)[3]), \
                   "r"((B)[0]), "r"((B)[1]))
#define MBAR_INIT(mbar, cnt) \
    asm volatile("mbarrier.init.shared.b64 [%0], %1;" \
                 :: "r"(mbar), "r"(cnt) : "memory")
#define MBAR_EXPECT_TX(mbar, bytes) \
    asm volatile("mbarrier.arrive.expect_tx.shared.b64 _, [%0], %1;" \
                 :: "r"(mbar), "r"(bytes) : "memory")
#define BULK_G2S(dst, src, bytes, mbar) \
    asm volatile("cp.async.bulk.shared::cta.global.mbarrier::complete_tx::bytes " \
                 "[%0], [%1], %2, [%3];" \
                 :: "r"(dst), "l"(src), "r"(bytes), "r"(mbar) : "memory")
#define MBAR_WAIT(mbar, parity) do { \
    unsigned _done = 0; \
    while (!_done) { \
        asm volatile("{\n\t.reg .pred p;\n\t" \
                     "mbarrier.try_wait.parity.acquire.cta.shared::cta.b64 " \
                     "p, [%1], %2, 0x989680;\n\t" \
                     "selp.b32 %0, 1, 0, p;\n\t}" \
                     : "=r"(_done) : "r"(mbar), "r"(parity) : "memory"); \
    } \
} while (0)

// Precomputed: W_eff split into bf16 hi/lo pairs, and U = I + V.
__device__ __nv_bfloat16 g_Whi[CCH][LSEQ];
__device__ __nv_bfloat16 g_Wlo[CCH][LSEQ];
__device__ float    g_U[AA * AA];
__device__ unsigned g_flag = 0;      // NPRE publishers
__device__ unsigned g_done = 0;      // end-of-launch reset

struct PreShared {                    // 22528 B
    float bufA[CCH][256];
    float bufB[CCH][256];
    float wsh[NREST * CCH * CCH * 3];
};
struct MainShared {                   // 26248 B
    float nat[256 * AA];              // 20480
    float Dp[8][AA][CCH];             //  5120 (valid a rows only)
    float g_sh[AA][CCH];              //   640
    unsigned long long mbar;
};
union KShared { PreShared pre; MainShared mn; };

// Adjoint of one conv(3,pad1)+avgpool(2) layer, block-cooperative.
template<int LEN2>
__device__ __forceinline__ void adj_layer(const float (*cur)[256],
                                          float (*nxt)[256],
                                          const float* __restrict__ w) {
    for (int idx = threadIdx.x; idx < CCH * LEN2; idx += 256) {
        const int i = idx / LEN2;
        const int p = idx % LEN2;
        float acc = 0.f;
        #pragma unroll
        for (int o = 0; o < CCH; ++o) {
            #pragma unroll
            for (int k = 0; k < 3; ++k) {
                const int q = p - k + 1;
                if (q >= 0 && q < LEN2)
                    acc += w[(o * CCH + i) * 3 + k] * 0.5f * cur[o][q >> 1];
            }
        }
        nxt[i][p] = acc;
    }
    __syncthreads();
}

// pack two fp32 into bf16x2 (lo in low half)
__device__ __forceinline__ unsigned pack_bf2(float lo, float hi) {
    __nv_bfloat162 u = __floats2bfloat162_rn(lo, hi);
    return *reinterpret_cast<unsigned*>(&u);
}

// ---------------------------------------------------------------------------
// Single fused kernel, grid 1033 (single wave at 8 blocks/SM).
// Blocks 0..8: W_eff (bf16 hi/lo) + U + zero out, publish g_flag.
// Blocks 9..1032: issue ONE 20KB cp.async.bulk (flies during the spin),
// nanosleep-spin on g_flag, then the R16 MMA body. Spinners wait only on
// blocks 0..8, which are first in the grid -> always wave-1 resident.
// ---------------------------------------------------------------------------
__global__ void __launch_bounds__(256, 8)
fused_kernel(const float* __restrict__ x,
             const float* __restrict__ lpm,
             const float* __restrict__ pm,
             const float* __restrict__ w_first,
             const float* __restrict__ w_rest,
             float* __restrict__ out) {
    __shared__ __align__(16) KShared sh;
    const int blk = blockIdx.x;
    const int tid = threadIdx.x;

    if (blk < NPRE) {
        // ================= precompute role =================
        if (blk < CCH) {
            PreShared& ps = sh.pre;
            for (int i = tid; i < NREST * CCH * CCH * 3; i += 256)
                ps.wsh[i] = w_rest[i];
            if (tid < CCH) ps.bufA[tid][0] = (tid == blk) ? 1.f : 0.f;
            __syncthreads();

            float (*cur)[256] = ps.bufA;
            float (*nxt)[256] = ps.bufB;
            float (*tmp)[256];
            #define STEP(L2, LI) \
                adj_layer<L2>(cur, nxt, ps.wsh + (LI) * 192); \
                tmp = cur; cur = nxt; nxt = tmp;
            STEP(2, 7)  STEP(4, 6)  STEP(8, 5)   STEP(16, 4)
            STEP(32, 3) STEP(64, 2) STEP(128, 1) STEP(256, 0)
            #undef STEP

            for (int p = tid; p < LSEQ; p += 256) {
                float acc = 0.f;
                #pragma unroll
                for (int o = 0; o < CCH; ++o) {
                    #pragma unroll
                    for (int k = 0; k < 3; ++k) {
                        const int q = p - k + 1;
                        if (q >= 0 && q < LSEQ)
                            acc += w_first[o * 3 + k] * 0.5f * cur[o][q >> 1];
                    }
                }
                const __nv_bfloat16 hi = __float2bfloat16(acc);
                g_Whi[blk][p] = hi;
                g_Wlo[blk][p] = __float2bfloat16(acc - __bfloat162float(hi));
            }
        } else {
            // U[a][i] = delta(a,i) + V[a][i]
            for (int idx = tid; idx < AA * AA; idx += 256) {
                const int a = idx / AA, i = idx % AA;
                float v = (a == i) ? 1.f : 0.f;
                if (i != a && i != AA - 1) {
                    const int r = (a < i) ? a : i;
                    const int c = (a < i) ? i : a;
                    float l = lpm[r * AA + c];
                    l = fminf(fmaxf(l, 1e-3f), 1.f);
                    v = l * pm[r * AA + c];
                }
                g_U[idx] = v;
            }
        }
        // Zero out: 20480 float4 split across the 9 blocks.
        {
            float4* o4 = reinterpret_cast<float4*>(out);
            const int lo = blk * 2276;
            const int hi = (lo + 2276 < 20480) ? lo + 2276 : 20480;
            for (int i = lo + tid; i < hi; i += 256)
                o4[i] = make_float4(0.f, 0.f, 0.f, 0.f);
        }
        __threadfence();
        __syncthreads();
        if (tid == 0) atomicAdd(&g_flag, 1u);
    } else {
        // ================= main role =================
        MainShared& ms = sh.mn;
        const int mb   = blk - NPRE;
        const int b    = mb >> 1;
        const int half = mb & 1;
        const int lane = tid & 31;
        const int w    = tid >> 5;
        const unsigned mbad = (unsigned)__cvta_generic_to_shared(&ms.mbar);

        if (tid == 0) MBAR_INIT(mbad, 1);
        __syncthreads();
        if (tid == 0) {
            MBAR_EXPECT_TX(mbad, 20480u);
            const char* src = reinterpret_cast<const char*>(x)
                            + (size_t)b * 40960 + half * 20480;
            BULK_G2S((unsigned)__cvta_generic_to_shared(ms.nat),
                     src, 20480u, mbad);
        }

        // Spin for W/U readiness; the bulk copy flies under this.
        if (tid == 0) {
            volatile unsigned* f = &g_flag;
            while (*f != (unsigned)NPRE) __nanosleep(128);
            __threadfence();
        }
        __syncthreads();

        // B fragments via LDG.32 from L2-hot g_Whi / g_Wlo.
        const int kbase = w * 32;
        const int c_n  = lane >> 2;
        const int kq   = 2 * (lane & 3);
        unsigned Bh[2][2], Bl[2][2];
        #pragma unroll
        for (int ks = 0; ks < 2; ++ks) {
            const int kcol = half * 256 + kbase + ks * 16 + kq;
            Bh[ks][0] = *reinterpret_cast<const unsigned*>(&g_Whi[c_n][kcol]);
            Bh[ks][1] = *reinterpret_cast<const unsigned*>(&g_Whi[c_n][kcol + 8]);
            Bl[ks][0] = *reinterpret_cast<const unsigned*>(&g_Wlo[c_n][kcol]);
            Bl[ks][1] = *reinterpret_cast<const unsigned*>(&g_Wlo[c_n][kcol + 8]);
        }

        MBAR_WAIT(mbad, 0u);

        // A fragments straight from nat; 8 MMAs (R14/R16-proven layout).
        const int r0 = lane >> 2;
        float C0[4] = {0.f, 0.f, 0.f, 0.f};
        float C1[4] = {0.f, 0.f, 0.f, 0.f};
        #pragma unroll
        for (int ks = 0; ks < 2; ++ks) {
            const int cb = kbase + ks * 16 + kq;
            const float* n0 = &ms.nat[cb * AA];
            unsigned A0[4];
            A0[0] = pack_bf2(n0[r0],              n0[AA + r0]);
            A0[1] = pack_bf2(n0[8 + r0],          n0[AA + 8 + r0]);
            A0[2] = pack_bf2(n0[8 * AA + r0],     n0[9 * AA + r0]);
            A0[3] = pack_bf2(n0[8 * AA + 8 + r0], n0[9 * AA + 8 + r0]);
            unsigned A1[4] = {0u, 0u, 0u, 0u};
            if (r0 < 4) {
                A1[0] = pack_bf2(n0[16 + r0],          n0[AA + 16 + r0]);
                A1[2] = pack_bf2(n0[8 * AA + 16 + r0], n0[9 * AA + 16 + r0]);
            }
            MMA_BF16(C0, A0, Bh[ks]);
            MMA_BF16(C0, A0, Bl[ks]);
            MMA_BF16(C1, A1, Bh[ks]);
            MMA_BF16(C1, A1, Bl[ks]);
        }

        // Park valid rows only (a < 20): C0 rows 0..15, C1[0..1] rows 16..19.
        {
            const int q2 = (lane & 3) * 2, tr = lane >> 2;
            *reinterpret_cast<float2*>(&ms.Dp[w][tr    ][q2]) =
                make_float2(C0[0], C0[1]);
            *reinterpret_cast<float2*>(&ms.Dp[w][tr + 8][q2]) =
                make_float2(C0[2], C0[3]);
            if (tr < 4)
                *reinterpret_cast<float2*>(&ms.Dp[w][tr + 16][q2]) =
                    make_float2(C1[0], C1[1]);
        }
        __syncthreads();

        if (tid < AA * CCH) {
            const int a = tid >> 3, c = tid & 7;
            float sum = 0.f;
            #pragma unroll
            for (int ww = 0; ww < 8; ++ww) sum += ms.Dp[ww][a][c];
            ms.g_sh[a][c] = sum;
        }
        __syncthreads();

        // out[b,i,c] += sum_a U[a][i] * g[a][c]  (2 halves via atomics)
        if (tid < AA * CCH) {
            const int i = tid >> 3;
            const int c = tid & 7;
            float r = 0.f;
            #pragma unroll
            for (int a = 0; a < AA; ++a)
                r += __ldg(&g_U[a * AA + i]) * ms.g_sh[a][c];
            atomicAdd(&out[(size_t)b * (AA * CCH) + tid], r);
        }
    }

    // Reset flags for the next graph replay (last block to finish).
    __syncthreads();
    if (tid == 0) {
        const unsigned d = atomicAdd(&g_done, 1u);
        if (d == (unsigned)(GRID - 1)) {
            g_done = 0u;
            g_flag = 0u;
            __threadfence();
        }
    }
}

// ---------------------------------------------------------------------------
extern "C" void kernel_launch(void* const* d_in, const int* in_sizes, int n_in,
                              void* d_out, int out_size) {
    const float* x       = (const float*)d_in[0];
    const float* lpm     = (const float*)d_in[2];
    const float* pm      = (const float*)d_in[3];
    const float* w_first = (const float*)d_in[4];
    const float* w_rest  = (const float*)d_in[5];
    float* out = (float*)d_out;

    fused_kernel<<<GRID, 256>>>(x, lpm, pm, w_first, w_rest, out);
}